// round 15
// baseline (speedup 1.0000x reference)
#include <cuda_runtime.h>

#define NCOEF 25
#define ROWS_PER_THREAD 4
#define THREADS 64
#define FLOATS_PER_THREAD (NCOEF * ROWS_PER_THREAD)   // 100 = 25 float4
#define F4_PER_THREAD (FLOATS_PER_THREAD / 4)         // 25

__device__ __forceinline__ void levinson25(float* a /* a[0..24], static idx */)
{
    #pragma unroll
    for (int m = 2; m <= NCOEF - 1; ++m) {
        const float km = a[m];            // a[m] == k[m], never overwritten
        int i = 1, j = m - 1;
        #pragma unroll
        for (; i < j; ++i, --j) {
            float ai = a[i], aj = a[j];
            a[i] = fmaf(km, aj, ai);
            a[j] = fmaf(km, ai, aj);
        }
        if (i == j) {
            float ai = a[i];
            a[i] = fmaf(km, ai, ai);
        }
    }
}

__global__ __launch_bounds__(THREADS, 24)
void parcor_reg_kernel(const float* __restrict__ in,
                       float* __restrict__ out,
                       int nrows)
{
    const long long tidg = (long long)blockIdx.x * THREADS + threadIdx.x;
    const long long row0 = tidg * ROWS_PER_THREAD;
    if (row0 >= (long long)nrows) return;

    if (row0 + ROWS_PER_THREAD <= (long long)nrows) {
        // ---- fast path: 4 rows = 25 contiguous float4, all in registers ----
        float a[FLOATS_PER_THREAD];

        const float4* __restrict__ g =
            reinterpret_cast<const float4*>(in + row0 * NCOEF);
        #pragma unroll
        for (int i = 0; i < F4_PER_THREAD; ++i) {
            float4 v = __ldcg(g + i);          // 25 independent LDG.128, front-batched
            a[4 * i + 0] = v.x;
            a[4 * i + 1] = v.y;
            a[4 * i + 2] = v.z;
            a[4 * i + 3] = v.w;
        }

        #pragma unroll
        for (int r = 0; r < ROWS_PER_THREAD; ++r)
            levinson25(a + r * NCOEF);         // static offsets after unroll

        float4* __restrict__ o =
            reinterpret_cast<float4*>(out + row0 * NCOEF);
        #pragma unroll
        for (int i = 0; i < F4_PER_THREAD; ++i) {
            float4 v;
            v.x = a[4 * i + 0];
            v.y = a[4 * i + 1];
            v.z = a[4 * i + 2];
            v.w = a[4 * i + 3];
            o[i] = v;
        }
    } else {
        // ---- tail: scalar per-row fallback ----
        #pragma unroll
        for (int r = 0; r < ROWS_PER_THREAD; ++r) {
            long long row = row0 + r;
            if (row >= (long long)nrows) break;
            float a[NCOEF];
            #pragma unroll
            for (int j = 0; j < NCOEF; ++j) a[j] = in[row * NCOEF + j];
            levinson25(a);
            #pragma unroll
            for (int j = 0; j < NCOEF; ++j) out[row * NCOEF + j] = a[j];
        }
    }
}

extern "C" void kernel_launch(void* const* d_in, const int* in_sizes, int n_in,
                              void* d_out, int out_size)
{
    const float* k = (const float*)d_in[0];
    float* out = (float*)d_out;
    int nrows = in_sizes[0] / NCOEF;   // 2097152 for the bench shape
    long long nthreads = ((long long)nrows + ROWS_PER_THREAD - 1) / ROWS_PER_THREAD;
    int blocks = (int)((nthreads + THREADS - 1) / THREADS);   // 8192 on bench shape
    parcor_reg_kernel<<<blocks, THREADS>>>(k, out, nrows);
}

// round 16
// speedup vs baseline: 2.2015x; 2.2015x over previous
#include <cuda_runtime.h>

#define NCOEF 25
#define ROWS_PER_THREAD 4
#define THREADS 64
#define FLOATS_PER_THREAD (NCOEF * ROWS_PER_THREAD)   // 100 = 25 float4
#define F4_PER_THREAD (FLOATS_PER_THREAD / 4)         // 25

// Levinson step-up on a[BASE .. BASE+24], every index a compile-time constant.
template <int BASE>
__device__ __forceinline__ void levinson25(float (&a)[FLOATS_PER_THREAD])
{
    #pragma unroll
    for (int m = 2; m <= NCOEF - 1; ++m) {
        const float km = a[BASE + m];       // a[m] == k[m], never overwritten
        int i = 1, j = m - 1;
        #pragma unroll
        for (; i < j; ++i, --j) {
            float ai = a[BASE + i], aj = a[BASE + j];
            a[BASE + i] = fmaf(km, aj, ai);
            a[BASE + j] = fmaf(km, ai, aj);
        }
        if (i == j) {
            float ai = a[BASE + i];
            a[BASE + i] = fmaf(km, ai, ai);
        }
    }
}

__global__ __launch_bounds__(THREADS)   // NO min-blocks: let ptxas use ~140 regs
void parcor_reg_kernel(const float* __restrict__ in,
                       float* __restrict__ out,
                       int nrows)
{
    const long long tidg = (long long)blockIdx.x * THREADS + threadIdx.x;
    const long long row0 = tidg * ROWS_PER_THREAD;
    if (row0 >= (long long)nrows) return;

    if (row0 + ROWS_PER_THREAD <= (long long)nrows) {
        // ---- fast path: 4 rows = 25 contiguous float4, all in registers ----
        float a[FLOATS_PER_THREAD];

        const float4* __restrict__ g =
            reinterpret_cast<const float4*>(in + row0 * NCOEF);
        #pragma unroll
        for (int i = 0; i < F4_PER_THREAD; ++i) {
            float4 v = __ldcg(g + i);          // 25 independent LDG.128
            a[4 * i + 0] = v.x;
            a[4 * i + 1] = v.y;
            a[4 * i + 2] = v.z;
            a[4 * i + 3] = v.w;
        }

        levinson25<0 * NCOEF>(a);
        levinson25<1 * NCOEF>(a);
        levinson25<2 * NCOEF>(a);
        levinson25<3 * NCOEF>(a);

        float4* __restrict__ o =
            reinterpret_cast<float4*>(out + row0 * NCOEF);
        #pragma unroll
        for (int i = 0; i < F4_PER_THREAD; ++i) {
            float4 v;
            v.x = a[4 * i + 0];
            v.y = a[4 * i + 1];
            v.z = a[4 * i + 2];
            v.w = a[4 * i + 3];
            o[i] = v;
        }
    } else {
        // ---- tail: scalar per-row fallback (bench shape never hits this) ----
        for (int r = 0; r < ROWS_PER_THREAD; ++r) {
            long long row = row0 + r;
            if (row >= (long long)nrows) break;
            float a[FLOATS_PER_THREAD];
            #pragma unroll
            for (int j = 0; j < NCOEF; ++j) a[j] = in[row * NCOEF + j];
            levinson25<0>(a);
            #pragma unroll
            for (int j = 0; j < NCOEF; ++j) out[row * NCOEF + j] = a[j];
        }
    }
}

extern "C" void kernel_launch(void* const* d_in, const int* in_sizes, int n_in,
                              void* d_out, int out_size)
{
    const float* k = (const float*)d_in[0];
    float* out = (float*)d_out;
    int nrows = in_sizes[0] / NCOEF;   // 2097152 for the bench shape
    long long nthreads = ((long long)nrows + ROWS_PER_THREAD - 1) / ROWS_PER_THREAD;
    int blocks = (int)((nthreads + THREADS - 1) / THREADS);   // 8192 on bench shape
    parcor_reg_kernel<<<blocks, THREADS>>>(k, out, nrows);
}